// round 14
// baseline (speedup 1.0000x reference)
#include <cuda_runtime.h>
#include <math.h>

#define HIDDEN   64
#define NBASIS   10
#define SEQ      96
#define BATCH    16384
#define NPAIR    (HIDDEN * NBASIS)     // 640
#define GTAB     128
#define NBLK     128                   // one wave on 148 SMs
#define NTHR     640

#define DOM_LO   (-6.0f)
#define DOM_H    (12.0f / (float)(GTAB - 4))
#define DOM_INVH ((float)(GTAB - 4) / 12.0f)

__device__ float2 g_table[GTAB];
__device__ unsigned int g_bar = 0;     // monotonic ticket barrier (replay-safe)

__device__ __forceinline__ float tanha(float v) {
    float r;
    asm("tanh.approx.f32 %0, %1;" : "=f"(r) : "f"(v));
    return r;
}

__global__ void __launch_bounds__(NTHR) k_fused(
    const float* __restrict__ x,
    const float* __restrict__ Wx,  const float* __restrict__ ax,
    const float* __restrict__ cx,  const float* __restrict__ Wc,
    const float* __restrict__ ac,  const float* __restrict__ cc,
    const float* __restrict__ Wout, float* __restrict__ out)
{
    __shared__ float hsh[HIDDEN];                       // 256 B
    __shared__ float psh[NPAIR];                        // 2.5 KB
    __shared__ float slots[4][NPAIR];                   // 10 KB
    __shared__ float sq[4][HIDDEN];                     // 1 KB
    __shared__ float phs[HIDDEN];                       // 256 B

    const int tid = threadIdx.x;
    const int g   = blockIdx.x;                         // one table point/block

    // ---- stage-3 addressing (needed for entry prefetch) -------------------
    const int q     = tid / 160;       // i-quarter [0,4)
    const int t5    = tid - q * 160;   // slot group [0,160)
    const int ibase = q * 16;
    const int s0 = 4 * t5;
    const float4* wb = reinterpret_cast<const float4*>(Wc) + t5 + ibase * 160;

    // ---- entry prefetches: x value + 8 weight vectors + Wout --------------
    const int  b  = blockIdx.x * (BATCH / NBLK) + tid;  // 128 per block
    float xv = 0.f;
    if (tid < BATCH / NBLK) xv = __ldg(x + b * SEQ + (SEQ - 1));

    float4 wvr = make_float4(0.f, 0.f, 0.f, 0.f);
    if (tid < 32) wvr = __ldg(reinterpret_cast<const float4*>(Wout) + tid);

    float4 wreg[8];
    #pragma unroll
    for (int ii = 0; ii < 8; ii++)
        wreg[ii] = __ldg(wb + ii * 160);

    // ======= stage 1: h[o] (tk inlined) ===================================
    if (tid < HIDDEN) {
        const float xg = DOM_LO + ((float)g - 1.5f) * DOM_H;
        float s = 0.f;
        #pragma unroll
        for (int k = 0; k < NBASIS; k++) {
            float tk = tanha(xg * __ldg(ax + k) + __ldg(cx + k));
            s += tk * __ldg(Wx + tid * NBASIS + k);
        }
        hsh[tid] = tanha(s);
    }
    __syncthreads();

    // ======= stage 2: p[640], 1 tanh per thread ===========================
    if (tid < NPAIR) {
        int i = tid / NBASIS;
        psh[tid] = tanha(hsh[i] * __ldg(ac + tid) + __ldg(cc + tid));
    }
    __syncthreads();

    // ======= stage 3: GEMV; first 8 i from regs, last 8 streamed ==========
    {
        const int k0 = s0 % 10, k1 = (s0 + 1) % 10,
                  k2 = (s0 + 2) % 10, k3 = (s0 + 3) % 10;
        const float* pw = psh + ibase * NBASIS;

        float a0 = 0.f, a1 = 0.f, a2 = 0.f, a3 = 0.f;
        #pragma unroll
        for (int ii = 8; ii < 16; ii++) {               // issue tail loads first
            float4 w = __ldg(wb + ii * 160);
            const float* pr = pw + ii * NBASIS;
            a0 = fmaf(pr[k0], w.x, a0);
            a1 = fmaf(pr[k1], w.y, a1);
            a2 = fmaf(pr[k2], w.z, a2);
            a3 = fmaf(pr[k3], w.w, a3);
        }
        #pragma unroll
        for (int ii = 0; ii < 8; ii++) {                // register-resident
            const float* pr = pw + ii * NBASIS;
            a0 = fmaf(pr[k0], wreg[ii].x, a0);
            a1 = fmaf(pr[k1], wreg[ii].y, a1);
            a2 = fmaf(pr[k2], wreg[ii].z, a2);
            a3 = fmaf(pr[k3], wreg[ii].w, a3);
        }
        slots[q][s0 + 0] = a0;
        slots[q][s0 + 1] = a1;
        slots[q][s0 + 2] = a2;
        slots[q][s0 + 3] = a3;
    }
    __syncthreads();

    // ======= stage 4a: partial sums, 256 threads (o, q) ===================
    if (tid < 256) {
        int o  = tid & 63;
        int qq = tid >> 6;
        const float* sl = &slots[qq][o * NBASIS];
        float s = 0.f;
        #pragma unroll
        for (int d = 0; d < NBASIS; d++) s += sl[d];
        sq[qq][o] = s;
    }
    __syncthreads();

    // ======= stage 4b: combine + tanh =====================================
    if (tid < HIDDEN) {
        phs[tid] = tanha((sq[0][tid] + sq[1][tid]) + (sq[2][tid] + sq[3][tid]));
    }
    __syncthreads();

    // ======= stage 5: head, warp 0; tid0 writes the table entry ===========
    if (tid < 32) {
        float c0 = phs[2 * tid] * wvr.x + phs[2 * tid + 1] * wvr.z;
        float c1 = phs[2 * tid] * wvr.y + phs[2 * tid + 1] * wvr.w;
        #pragma unroll
        for (int s = 16; s > 0; s >>= 1) {
            c0 += __shfl_xor_sync(0xffffffffu, c0, s);
            c1 += __shfl_xor_sync(0xffffffffu, c1, s);
        }
        if (tid == 0)
            g_table[g] = make_float2(c0, c1);
    }

    // ---- precompute interp coefficients (independent of the table) -------
    float wA = 0.f, wB = 0.f, wC = 0.f, wD = 0.f;
    int i0 = 1;
    if (tid < BATCH / NBLK) {
        float t = (xv - DOM_LO) * DOM_INVH + 1.5f;
        i0 = (int)floorf(t);
        i0 = max(1, min(GTAB - 3, i0));
        float u = t - (float)i0;
        float um1 = u - 1.f, um2 = u - 2.f, up1 = u + 1.f;
        wA = -u * um1 * um2 * (1.f / 6.f);
        wB =  up1 * um1 * um2 * 0.5f;
        wC = -up1 * u * um2 * 0.5f;
        wD =  up1 * u * um1 * (1.f / 6.f);
    }

    // ======= grid barrier: release arrival + backoff acquire spin =========
    if (tid == 0) {
        unsigned int my;
        asm volatile("atom.release.gpu.global.add.u32 %0, [%1], %2;"
                     : "=r"(my) : "l"(&g_bar), "r"(1u) : "memory");
        unsigned int target = (my / NBLK + 1u) * NBLK;
        unsigned int cur;
        while (true) {
            asm volatile("ld.acquire.gpu.global.u32 %0, [%1];"
                         : "=r"(cur) : "l"(&g_bar) : "memory");
            if (cur >= target) break;
            __nanosleep(64);
        }
    }
    __syncthreads();

    // ======= phase 2: interpolate (direct L2 gathers, no smem staging) ====
    if (tid < BATCH / NBLK) {
        const float2* gt = g_table + (i0 - 1);
        float2 fA, fB, fC, fD;
        asm volatile("ld.global.cg.v2.f32 {%0, %1}, [%2];"
                     : "=f"(fA.x), "=f"(fA.y) : "l"(gt + 0));
        asm volatile("ld.global.cg.v2.f32 {%0, %1}, [%2];"
                     : "=f"(fB.x), "=f"(fB.y) : "l"(gt + 1));
        asm volatile("ld.global.cg.v2.f32 {%0, %1}, [%2];"
                     : "=f"(fC.x), "=f"(fC.y) : "l"(gt + 2));
        asm volatile("ld.global.cg.v2.f32 {%0, %1}, [%2];"
                     : "=f"(fD.x), "=f"(fD.y) : "l"(gt + 3));
        float o0 = wA * fA.x + wB * fB.x + wC * fC.x + wD * fD.x;
        float o1 = wA * fA.y + wB * fB.y + wC * fC.y + wD * fD.y;
        reinterpret_cast<float2*>(out)[b] = make_float2(o0, o1);
    }
}

// ---------------------------------------------------------------------------
extern "C" void kernel_launch(void* const* d_in, const int* in_sizes, int n_in,
                              void* d_out, int out_size) {
    const float* x    = (const float*)d_in[0];
    const float* Wx   = (const float*)d_in[1];
    const float* ax   = (const float*)d_in[2];
    const float* cx   = (const float*)d_in[3];
    // d_in[4..6] = Wh, ah, ch -- mathematically unused by the reference
    const float* Wc   = (const float*)d_in[7];
    const float* ac   = (const float*)d_in[8];
    const float* cc   = (const float*)d_in[9];
    const float* Wout = (const float*)d_in[10];

    k_fused<<<NBLK, NTHR>>>(x, Wx, ax, cx, Wc, ac, cc, Wout, (float*)d_out);
}

// round 17
// speedup vs baseline: 1.2316x; 1.2316x over previous
#include <cuda_runtime.h>
#include <math.h>

#define HIDDEN   64
#define NBASIS   10
#define SEQ      96
#define BATCH    16384
#define NPAIR    (HIDDEN * NBASIS)     // 640
#define GTAB     128
#define NBLK     128                   // one wave on 148 SMs
#define NTHR     640

#define DOM_LO   (-6.0f)
#define DOM_H    (12.0f / (float)(GTAB - 4))
#define DOM_INVH ((float)(GTAB - 4) / 12.0f)

__device__ float2 g_table[GTAB];
__device__ unsigned int g_bar = 0;     // monotonic ticket barrier (replay-safe)

__device__ __forceinline__ float tanha(float v) {
    float r;
    asm("tanh.approx.f32 %0, %1;" : "=f"(r) : "f"(v));
    return r;
}

__global__ void __launch_bounds__(NTHR) k_fused(
    const float* __restrict__ x,
    const float* __restrict__ Wx,  const float* __restrict__ ax,
    const float* __restrict__ cx,  const float* __restrict__ Wc,
    const float* __restrict__ ac,  const float* __restrict__ cc,
    const float* __restrict__ Wout, float* __restrict__ out)
{
    __shared__ float hsh[HIDDEN];                       // 256 B
    __shared__ float psh[NPAIR];                        // 2.5 KB
    __shared__ float slots[4][NPAIR];                   // 10 KB
    __shared__ float phs[HIDDEN];                       // 256 B
    __shared__ float2 stab[GTAB];                       // 1 KB

    const int tid = threadIdx.x;
    const int g   = blockIdx.x;                         // one table point/block

    // ---- stage-3 addressing (needed for entry prefetch) -------------------
    const int q     = tid / 160;       // i-quarter [0,4)
    const int t5    = tid - q * 160;   // slot group [0,160)
    const int ibase = q * 16;
    const int s0 = 4 * t5;
    const float4* wb = reinterpret_cast<const float4*>(Wc) + t5 + ibase * 160;

    // ---- entry prefetches: x value + first 8 weight vectors ---------------
    const int  b  = blockIdx.x * (BATCH / NBLK) + tid;  // 128 per block
    float xv = 0.f;
    if (tid < BATCH / NBLK) xv = __ldg(x + b * SEQ + (SEQ - 1));

    float4 wreg[8];
    #pragma unroll
    for (int ii = 0; ii < 8; ii++)
        wreg[ii] = __ldg(wb + ii * 160);

    // ======= stage 1: h[o] (tk inlined, no extra sync) ====================
    if (tid < HIDDEN) {
        const float xg = DOM_LO + ((float)g - 1.5f) * DOM_H;
        float s = 0.f;
        #pragma unroll
        for (int k = 0; k < NBASIS; k++) {
            float tk = tanha(xg * __ldg(ax + k) + __ldg(cx + k));
            s += tk * __ldg(Wx + tid * NBASIS + k);
        }
        hsh[tid] = tanha(s);
    }
    __syncthreads();

    // ======= stage 2: p[640], 1 tanh per thread ===========================
    if (tid < NPAIR) {
        int i = tid / NBASIS;
        psh[tid] = tanha(hsh[i] * __ldg(ac + tid) + __ldg(cc + tid));
    }
    __syncthreads();

    // ======= stage 3: GEMV; first 8 i from regs, last 8 streamed ==========
    {
        const int k0 = s0 % 10, k1 = (s0 + 1) % 10,
                  k2 = (s0 + 2) % 10, k3 = (s0 + 3) % 10;
        const float* pw = psh + ibase * NBASIS;

        float a0 = 0.f, a1 = 0.f, a2 = 0.f, a3 = 0.f;
        #pragma unroll
        for (int ii = 8; ii < 16; ii++) {               // issue tail loads first
            float4 w = __ldg(wb + ii * 160);
            const float* pr = pw + ii * NBASIS;
            a0 = fmaf(pr[k0], w.x, a0);
            a1 = fmaf(pr[k1], w.y, a1);
            a2 = fmaf(pr[k2], w.z, a2);
            a3 = fmaf(pr[k3], w.w, a3);
        }
        #pragma unroll
        for (int ii = 0; ii < 8; ii++) {                // register-resident
            const float* pr = pw + ii * NBASIS;
            a0 = fmaf(pr[k0], wreg[ii].x, a0);
            a1 = fmaf(pr[k1], wreg[ii].y, a1);
            a2 = fmaf(pr[k2], wreg[ii].z, a2);
            a3 = fmaf(pr[k3], wreg[ii].w, a3);
        }
        slots[q][s0 + 0] = a0;
        slots[q][s0 + 1] = a1;
        slots[q][s0 + 2] = a2;
        slots[q][s0 + 3] = a3;
    }
    __syncthreads();

    // ======= stage 4: phi[o] = tanh(sum of 40 slots) ======================
    if (tid < HIDDEN) {
        float s = 0.f;
        #pragma unroll
        for (int qq = 0; qq < 4; qq++) {
            const float* sl = &slots[qq][tid * NBASIS];
            #pragma unroll
            for (int d = 0; d < NBASIS; d++) s += sl[d];
        }
        phs[tid] = tanha(s);
    }
    __syncthreads();

    // ======= stage 5: head, warp 0; tid0 writes the table entry ===========
    if (tid < 32) {
        float4 wv = __ldg(reinterpret_cast<const float4*>(Wout) + tid);
        float c0 = phs[2 * tid] * wv.x + phs[2 * tid + 1] * wv.z;
        float c1 = phs[2 * tid] * wv.y + phs[2 * tid + 1] * wv.w;
        #pragma unroll
        for (int s = 16; s > 0; s >>= 1) {
            c0 += __shfl_xor_sync(0xffffffffu, c0, s);
            c1 += __shfl_xor_sync(0xffffffffu, c1, s);
        }
        if (tid == 0)
            g_table[g] = make_float2(c0, c1);
    }

    // ---- precompute interp coefficients (independent of the table) -------
    float wA = 0.f, wB = 0.f, wC = 0.f, wD = 0.f;
    int i0 = 1;
    if (tid < BATCH / NBLK) {
        float t = (xv - DOM_LO) * DOM_INVH + 1.5f;
        i0 = (int)floorf(t);
        i0 = max(1, min(GTAB - 3, i0));
        float u = t - (float)i0;
        float um1 = u - 1.f, um2 = u - 2.f, up1 = u + 1.f;
        wA = -u * um1 * um2 * (1.f / 6.f);
        wB =  up1 * um1 * um2 * 0.5f;
        wC = -up1 * u * um2 * 0.5f;
        wD =  up1 * u * um1 * (1.f / 6.f);
    }

    // ======= grid barrier: release arrival + acquire spin (tid0 only) =====
    // tid0 wrote g_table[g] itself, so release on its arrival publishes it.
    if (tid == 0) {
        unsigned int my;
        asm volatile("atom.release.gpu.global.add.u32 %0, [%1], %2;"
                     : "=r"(my) : "l"(&g_bar), "r"(1u) : "memory");
        unsigned int target = (my / NBLK + 1u) * NBLK;
        unsigned int cur;
        do {
            asm volatile("ld.acquire.gpu.global.u32 %0, [%1];"
                         : "=r"(cur) : "l"(&g_bar) : "memory");
        } while (cur < target);
    }
    __syncthreads();

    // ======= phase 2: interpolate =========================================
    if (tid < GTAB) {
        float2 v;
        asm volatile("ld.global.cg.v2.f32 {%0, %1}, [%2];"
                     : "=f"(v.x), "=f"(v.y) : "l"(g_table + tid));
        stab[tid] = v;
    }
    __syncthreads();

    if (tid < BATCH / NBLK) {
        float2 fA = stab[i0 - 1];
        float2 fB = stab[i0];
        float2 fC = stab[i0 + 1];
        float2 fD = stab[i0 + 2];
        float o0 = wA * fA.x + wB * fB.x + wC * fC.x + wD * fD.x;
        float o1 = wA * fA.y + wB * fB.y + wC * fC.y + wD * fD.y;
        reinterpret_cast<float2*>(out)[b] = make_float2(o0, o1);
    }
}

// ---------------------------------------------------------------------------
extern "C" void kernel_launch(void* const* d_in, const int* in_sizes, int n_in,
                              void* d_out, int out_size) {
    const float* x    = (const float*)d_in[0];
    const float* Wx   = (const float*)d_in[1];
    const float* ax   = (const float*)d_in[2];
    const float* cx   = (const float*)d_in[3];
    // d_in[4..6] = Wh, ah, ch -- mathematically unused by the reference
    const float* Wc   = (const float*)d_in[7];
    const float* ac   = (const float*)d_in[8];
    const float* cc   = (const float*)d_in[9];
    const float* Wout = (const float*)d_in[10];

    k_fused<<<NBLK, NTHR>>>(x, Wx, ax, cx, Wc, ac, cc, Wout, (float*)d_out);
}